// round 17
// baseline (speedup 1.0000x reference)
#include <cuda_runtime.h>

// Problem constants
#define HWD 256
#define CH_STRIDE (HWD * HWD)   // 65536 floats per channel plane
#define HB 128                  // h-rows per CTA
#define THREADS 512

// Shared buffers:
//   bufA    [128][256] : Qs (phase 1) -> S/P (softmax, phase 3)
//   bufB[2] [32][260]  : double-buffered K-chunks (phase 1) / V-chunks (phase 3).
//   Pipeline: slice LDGs issue BEFORE each 8-dw GEMM sub-block, projection+STS
//   happen AFTER it -> x2 latency hides under ~370 issue-slots of FMA work.
#define ST_A 256
#define ST_B 260
#define BUFA_FLOATS (128 * ST_A)                  // 32768
#define BUFB_FLOATS (32 * ST_B)                   // 8320 per buffer
#define SMEM_FLOATS (BUFA_FLOATS + 2 * BUFB_FLOATS)   // 49408
#define SMEM_BYTES  (SMEM_FLOATS * 4)                 // 197632

typedef unsigned long long u64;

__device__ __forceinline__ u64 pk2(float x, float y) {
    u64 r; asm("mov.b64 %0, {%1, %2};" : "=l"(r) : "f"(x), "f"(y)); return r;
}
__device__ __forceinline__ void upk2(u64 v, float &x, float &y) {
    asm("mov.b64 {%0, %1}, %2;" : "=f"(x), "=f"(y) : "l"(v));
}
// Packed dual-fp32 FMA: d = a * b + d. Only path to full fp32 rate on sm_103a.
__device__ __forceinline__ void fma2(u64 &d, u64 a, u64 b) {
    asm("fma.rn.f32x2 %0, %1, %2, %0;" : "+l"(d) : "l"(a), "l"(b));
}

__global__ void __launch_bounds__(THREADS, 1)
fused_conv_attn_kernel(const float* __restrict__ x1, const float* __restrict__ x2,
                       const float* __restrict__ Wq, const float* __restrict__ bq,
                       const float* __restrict__ Wk, const float* __restrict__ bk,
                       const float* __restrict__ Wv, const float* __restrict__ bv,
                       const float* __restrict__ Wa, const float* __restrict__ ba,
                       float* __restrict__ out)
{
    extern __shared__ float sm[];
    float* bufA = sm;                    // Qs -> S/P
    float* bufB = sm + BUFA_FLOATS;      // two [32][260] chunk buffers

    const int o   = blockIdx.x;   // 0..31 output channel
    const int hb  = blockIdx.y;   // 0..1  h block
    const int b   = blockIdx.z;   // 0..31 batch
    const int tid = threadIdx.x;
    const int lane = tid & 31;
    const int warpq = tid >> 5;   // warp id (softmax rows / fill g-groups)
    const int tx  = tid & 15;     // 16 column groups (4 cols each, +64m)
    const int ty  = tid >> 4;     // 32 row groups (4 rows each)

    const float* x1b = x1 + (size_t)b * 3 * CH_STRIDE;
    const float* x2b = x2 + (size_t)b * 3 * CH_STRIDE;
    const int h0g = hb * HB;

    // Projection weights needed inside the pipelined loops (hoisted).
    const float k0w = Wk[o*3+0], k1w = Wk[o*3+1], k2w = Wk[o*3+2], bbk = bk[o];
    const float v0w = Wv[o*3+0], v1w = Wv[o*3+1], v2w = Wv[o*3+2], bbv = bv[o];

    // V-fill thread mapping (used in prefill + phase 3)
    const int wiv = (tid & 63) * 4;
    const int gv  = (tid >> 6) * 4;   // + sub -> local g row in [0,32)

    // ---------------- Q fill: bufA[h][w] = Wq . x1[:,h,w] + bq (float4, coalesced)
    {
        const float w0 = Wq[o*3+0], w1 = Wq[o*3+1], w2 = Wq[o*3+2], bb = bq[o];
        const int wi = (tid & 63) * 4;
        const int hbase = (tid >> 6) * 16;
        #pragma unroll 4
        for (int k = 0; k < 16; ++k) {
            const int h = hbase + k;
            const float* p = x1b + (size_t)(h0g + h) * HWD + wi;
            float4 c0v = *(const float4*)(p);
            float4 c1v = *(const float4*)(p + CH_STRIDE);
            float4 c2v = *(const float4*)(p + 2 * CH_STRIDE);
            float4 r;
            r.x = bb + w0*c0v.x + w1*c1v.x + w2*c2v.x;
            r.y = bb + w0*c0v.y + w1*c1v.y + w2*c2v.y;
            r.z = bb + w0*c0v.z + w1*c1v.z + w2*c2v.z;
            r.w = bb + w0*c0v.w + w1*c1v.w + w2*c2v.w;
            *(float4*)&bufA[h * ST_A + wi] = r;
        }
    }

    // ---------------- Prefill K chunk 0 into buffer 0 (transposed [dw][g]).
    {
        #pragma unroll 4
        for (int k = 0; k < 16; ++k) {
            const int g = warpq * 16 + k;
            const float* p = x2b + (size_t)g * HWD + lane;   // w0 = 0
            float c0 = p[0], c1 = p[CH_STRIDE], c2 = p[2*CH_STRIDE];
            bufB[lane * ST_B + g] = bbk + k0w*c0 + k1w*c1 + k2w*c2;
        }
    }
    __syncthreads();

    // ---------------- Phase 1: S[128h][256g] in registers (4h x 16g per thread),
    // 8 chunks of 32 dw, double-buffered with LDG-early/STS-late pipelining.
    u64 sacc[4][8];
    #pragma unroll
    for (int i = 0; i < 4; ++i)
        #pragma unroll
        for (int m = 0; m < 8; ++m) sacc[i][m] = 0ull;

    for (int wt = 0; wt < 8; ++wt) {
        float* Bc = bufB + (wt & 1) * BUFB_FLOATS;
        float* Bn = bufB + ((wt & 1) ^ 1) * BUFB_FLOATS;
        const int w0 = wt * 32;

        for (int sub = 0; sub < 4; ++sub) {
            // ---- issue LDGs for next-chunk slice (values parked in regs) ----
            float kc0[4], kc1[4], kc2[4];        // K slice (wt < 7)
            float4 vc0, vc1, vc2;                // V prefill slice (wt == 7)
            if (wt < 7) {
                const int w0n = w0 + 32;
                #pragma unroll
                for (int kk = 0; kk < 4; ++kk) {
                    const int g = warpq * 16 + sub * 4 + kk;
                    const float* p = x2b + (size_t)g * HWD + w0n + lane;
                    kc0[kk] = p[0];
                    kc1[kk] = p[CH_STRIDE];
                    kc2[kk] = p[2*CH_STRIDE];
                }
            } else {
                const int g = gv + sub;
                const float* p = x2b + (size_t)g * HWD + wiv;
                vc0 = *(const float4*)(p);
                vc1 = *(const float4*)(p + CH_STRIDE);
                vc2 = *(const float4*)(p + 2 * CH_STRIDE);
            }

            // ---- GEMM: 8 dw of current chunk (hides the LDG latency) ----
            #pragma unroll
            for (int dq = 0; dq < 2; ++dq) {
                const int dw4 = sub * 8 + dq * 4;
                float4 qv[4];
                #pragma unroll
                for (int i = 0; i < 4; ++i)
                    qv[i] = *(const float4*)&bufA[(4*ty + i) * ST_A + w0 + dw4];
                #pragma unroll
                for (int u = 0; u < 4; ++u) {
                    const float* kr = &Bc[(dw4 + u) * ST_B + 4 * tx];
                    ulonglong2 K0 = *(const ulonglong2*)(kr);
                    ulonglong2 K1 = *(const ulonglong2*)(kr + 64);
                    ulonglong2 K2 = *(const ulonglong2*)(kr + 128);
                    ulonglong2 K3 = *(const ulonglong2*)(kr + 192);
                    #pragma unroll
                    for (int i = 0; i < 4; ++i) {
                        const float q = (&qv[i].x)[u];
                        u64 qq = pk2(q, q);
                        fma2(sacc[i][0], qq, K0.x); fma2(sacc[i][1], qq, K0.y);
                        fma2(sacc[i][2], qq, K1.x); fma2(sacc[i][3], qq, K1.y);
                        fma2(sacc[i][4], qq, K2.x); fma2(sacc[i][5], qq, K2.y);
                        fma2(sacc[i][6], qq, K3.x); fma2(sacc[i][7], qq, K3.y);
                    }
                }
            }

            // ---- projection + STS for the parked slice ----
            if (wt < 7) {
                #pragma unroll
                for (int kk = 0; kk < 4; ++kk) {
                    const int g = warpq * 16 + sub * 4 + kk;
                    Bn[lane * ST_B + g] = bbk + k0w*kc0[kk] + k1w*kc1[kk] + k2w*kc2[kk];
                }
            } else {
                const int g = gv + sub;
                float4 r;
                r.x = bbv + v0w*vc0.x + v1w*vc1.x + v2w*vc2.x;
                r.y = bbv + v0w*vc0.y + v1w*vc1.y + v2w*vc2.y;
                r.z = bbv + v0w*vc0.z + v1w*vc1.z + v2w*vc2.z;
                r.w = bbv + v0w*vc0.w + v1w*vc1.w + v2w*vc2.w;
                *(float4*)&Bn[g * ST_B + wiv] = r;
            }
        }
        __syncthreads();   // next chunk fully written; current fully read
    }

    // ---------------- Epilogue: S = sacc/256 + A-term (direct x2 read) -> bufA.
    // Rows warp-private (thread wrote/read only its own 4 rows).
    {
        const float a0w = Wa[o*3+0], a1w = Wa[o*3+1], a2w = Wa[o*3+2], bba = ba[o];
        const float inv = 1.0f / 256.0f;
        #pragma unroll
        for (int i = 0; i < 4; ++i) {
            const int h = 4 * ty + i;
            #pragma unroll
            for (int m = 0; m < 4; ++m) {
                float s0, s1, s2, s3;
                upk2(sacc[i][2*m],     s0, s1);
                upk2(sacc[i][2*m + 1], s2, s3);
                const float* pa = x2b + (size_t)(h0g + h) * HWD + 64*m + 4*tx;
                float4 a0 = *(const float4*)(pa);
                float4 a1 = *(const float4*)(pa + CH_STRIDE);
                float4 a2 = *(const float4*)(pa + 2*CH_STRIDE);
                float4 r;
                r.x = s0*inv + bba + a0w*a0.x + a1w*a1.x + a2w*a2.x;
                r.y = s1*inv + bba + a0w*a0.y + a1w*a1.y + a2w*a2.y;
                r.z = s2*inv + bba + a0w*a0.z + a1w*a1.z + a2w*a2.z;
                r.w = s3*inv + bba + a0w*a0.w + a1w*a1.w + a2w*a2.w;
                *(float4*)&bufA[h * ST_A + 64*m + 4*tx] = r;
            }
        }
    }
    __syncwarp();

    // ---------------- Softmax in place (warp per 8 rows; rows warp-private)
    {
        #pragma unroll 2
        for (int rr = 0; rr < 8; ++rr) {
            float* row = &bufA[(warpq * 8 + rr) * ST_A];
            float4 v0 = *(float4*)&row[lane * 4];
            float4 v1 = *(float4*)&row[128 + lane * 4];
            float m = fmaxf(fmaxf(fmaxf(v0.x, v0.y), fmaxf(v0.z, v0.w)),
                            fmaxf(fmaxf(v1.x, v1.y), fmaxf(v1.z, v1.w)));
            #pragma unroll
            for (int off = 16; off; off >>= 1)
                m = fmaxf(m, __shfl_xor_sync(0xffffffffu, m, off));
            v0.x = __expf(v0.x - m); v0.y = __expf(v0.y - m);
            v0.z = __expf(v0.z - m); v0.w = __expf(v0.w - m);
            v1.x = __expf(v1.x - m); v1.y = __expf(v1.y - m);
            v1.z = __expf(v1.z - m); v1.w = __expf(v1.w - m);
            float s = v0.x + v0.y + v0.z + v0.w + v1.x + v1.y + v1.z + v1.w;
            #pragma unroll
            for (int off = 16; off; off >>= 1)
                s += __shfl_xor_sync(0xffffffffu, s, off);
            const float rinv = 1.0f / s;
            v0.x *= rinv; v0.y *= rinv; v0.z *= rinv; v0.w *= rinv;
            v1.x *= rinv; v1.y *= rinv; v1.z *= rinv; v1.w *= rinv;
            *(float4*)&row[lane * 4] = v0;
            *(float4*)&row[128 + lane * 4] = v1;
        }
    }
    __syncwarp();   // P rows are read warp-privately in phase 3

    // ---------------- Phase 3: O = P V, 8 chunks of 32 g, double-buffered.
    // V chunk 0 already resides in buffer 0 (prefilled during phase-1 chunk 7).
    u64 oacc[4][8];
    #pragma unroll
    for (int i = 0; i < 4; ++i)
        #pragma unroll
        for (int m = 0; m < 8; ++m) oacc[i][m] = 0ull;

    for (int gt = 0; gt < 8; ++gt) {
        float* Bc = bufB + (gt & 1) * BUFB_FLOATS;
        float* Bn = bufB + ((gt & 1) ^ 1) * BUFB_FLOATS;
        const int pcol = gt * 32;

        for (int sub = 0; sub < 4; ++sub) {
            // ---- issue LDGs for next V slice (values parked in regs) ----
            float4 vc0, vc1, vc2;
            if (gt < 7) {
                const int g = gv + sub;
                const float* p = x2b + (size_t)((gt + 1) * 32 + g) * HWD + wiv;
                vc0 = *(const float4*)(p);
                vc1 = *(const float4*)(p + CH_STRIDE);
                vc2 = *(const float4*)(p + 2 * CH_STRIDE);
            }

            // ---- GEMM: 8 g of current chunk (hides the LDG latency) ----
            #pragma unroll
            for (int dq = 0; dq < 2; ++dq) {
                const int g4 = sub * 8 + dq * 4;
                float4 pv[4];
                #pragma unroll
                for (int i = 0; i < 4; ++i)
                    pv[i] = *(const float4*)&bufA[(4*ty + i) * ST_A + pcol + g4];
                #pragma unroll
                for (int u = 0; u < 4; ++u) {
                    const float* vr = &Bc[(g4 + u) * ST_B + 4 * tx];
                    ulonglong2 V0 = *(const ulonglong2*)(vr);
                    ulonglong2 V1 = *(const ulonglong2*)(vr + 64);
                    ulonglong2 V2 = *(const ulonglong2*)(vr + 128);
                    ulonglong2 V3 = *(const ulonglong2*)(vr + 192);
                    #pragma unroll
                    for (int i = 0; i < 4; ++i) {
                        const float p = (&pv[i].x)[u];
                        u64 pp = pk2(p, p);
                        fma2(oacc[i][0], pp, V0.x); fma2(oacc[i][1], pp, V0.y);
                        fma2(oacc[i][2], pp, V1.x); fma2(oacc[i][3], pp, V1.y);
                        fma2(oacc[i][4], pp, V2.x); fma2(oacc[i][5], pp, V2.y);
                        fma2(oacc[i][6], pp, V3.x); fma2(oacc[i][7], pp, V3.y);
                    }
                }
            }

            // ---- projection + STS for the parked V slice ----
            if (gt < 7) {
                const int g = gv + sub;
                float4 r;
                r.x = bbv + v0w*vc0.x + v1w*vc1.x + v2w*vc2.x;
                r.y = bbv + v0w*vc0.y + v1w*vc1.y + v2w*vc2.y;
                r.z = bbv + v0w*vc0.z + v1w*vc1.z + v2w*vc2.z;
                r.w = bbv + v0w*vc0.w + v1w*vc1.w + v2w*vc2.w;
                *(float4*)&Bn[g * ST_B + wiv] = r;
            }
        }
        __syncthreads();
    }

    // ---------------- Output: [b][o][h][w], float4 coalesced
    float* ob = out + ((size_t)(b * 32 + o) * HWD + h0g) * HWD;
    #pragma unroll
    for (int i = 0; i < 4; ++i) {
        const int h = 4 * ty + i;
        #pragma unroll
        for (int m = 0; m < 4; ++m) {
            float4 r;
            upk2(oacc[i][2 * m],     r.x, r.y);
            upk2(oacc[i][2 * m + 1], r.z, r.w);
            *(float4*)&ob[(size_t)h * HWD + 64 * m + 4 * tx] = r;
        }
    }
}

extern "C" void kernel_launch(void* const* d_in, const int* in_sizes, int n_in,
                              void* d_out, int out_size)
{
    const float* x1 = (const float*)d_in[0];
    const float* x2 = (const float*)d_in[1];
    const float* Wq = (const float*)d_in[2];
    const float* bq = (const float*)d_in[3];
    const float* Wk = (const float*)d_in[4];
    const float* bk = (const float*)d_in[5];
    const float* Wv = (const float*)d_in[6];
    const float* bv = (const float*)d_in[7];
    const float* Wa = (const float*)d_in[8];
    const float* ba = (const float*)d_in[9];
    float* out = (float*)d_out;

    cudaFuncSetAttribute(fused_conv_attn_kernel,
                         cudaFuncAttributeMaxDynamicSharedMemorySize, SMEM_BYTES);

    dim3 grid(32, 2, 32);   // (o, h-block, b): consecutive CTAs share b -> x2[b] L2-resident
    fused_conv_attn_kernel<<<grid, THREADS, SMEM_BYTES>>>(
        x1, x2, Wq, bq, Wk, bk, Wv, bv, Wa, ba, out);
}